// round 1
// baseline (speedup 1.0000x reference)
#include <cuda_runtime.h>
#include <cuda_bf16.h>
#include <cstdint>

// ---------------------------------------------------------------------------
// PhaseTracker: encode -> evolve -> similarity GEMM (f32x2) -> parallel greedy
// ---------------------------------------------------------------------------

#define N_DET   4096
#define DIM     128
#define HID     64
#define NOSC    28
#define KTOT    56          // 2*NOSC (cos|sin)
#define TWO_PI_F 6.283185307179586f
#define INV_2PI  0.15915494309189535f
#define DENOM_F  28.000010583006244f   // (sqrt(28)+1e-6)^2

// scratch (device globals; no allocation allowed)
__device__ float g_phase[N_DET * NOSC];
__device__ float g_amp[N_DET * NOSC];
__device__ float g_A[N_DET * 112];          // A rows: [c0 c0 c1 c1 ... s27 s27] (duplicated pairs)
__device__ float g_B[KTOT * N_DET];         // B k-major: g_B[k][j]
__device__ unsigned long long g_rowbest[N_DET];
__device__ unsigned long long g_colbest[N_DET];

__device__ __forceinline__ float mod2pi(float v) {
    return v - floorf(v * INV_2PI) * TWO_PI_F;
}
__device__ __forceinline__ float softplusf(float x) {
    return fmaxf(x, 0.0f) + log1pf(expf(-fabsf(x)));
}
__device__ __forceinline__ unsigned ordf(float x) {
    unsigned u = __float_as_uint(x);
    return (u & 0x80000000u) ? ~u : (u | 0x80000000u);
}
__device__ __forceinline__ void ffma2(unsigned long long& d,
                                      unsigned long long a,
                                      unsigned long long b) {
    asm("fma.rn.f32x2 %0, %1, %2, %0;" : "+l"(d) : "l"(a), "l"(b));
}

// ---------------------------------------------------------------------------
// init: zero the atomic-max scratch
// ---------------------------------------------------------------------------
__global__ void init_kernel() {
    int i = blockIdx.x * blockDim.x + threadIdx.x;
    if (i < N_DET) { g_rowbest[i] = 0ull; g_colbest[i] = 0ull; }
}

// ---------------------------------------------------------------------------
// Encode: two 2-layer MLPs. Weights transposed into shared once per block.
// 256 threads per block, 32 rows per block (2 rows per inner iteration).
// ---------------------------------------------------------------------------
#define ENC_W1STR 132     // padded row stride for [HID][DIM] transposed W1
#define ENC_W2STR 68      // padded row stride for [NOSC][HID] transposed W2
#define ENC_SMEM_FLOATS (2*HID*ENC_W1STR + 2*NOSC*ENC_W2STR + 256 + 256)

__global__ __launch_bounds__(256, 2)
void encode_kernel(const float* __restrict__ det_t, const float* __restrict__ det_t1,
                   const float* __restrict__ Wp1, const float* __restrict__ bp1,
                   const float* __restrict__ Wp2, const float* __restrict__ bp2,
                   const float* __restrict__ Wa1, const float* __restrict__ ba1,
                   const float* __restrict__ Wa2, const float* __restrict__ ba2) {
    extern __shared__ float sm[];
    float* wp1T = sm;                          // HID x ENC_W1STR
    float* wa1T = wp1T + HID * ENC_W1STR;
    float* wp2T = wa1T + HID * ENC_W1STR;      // NOSC x ENC_W2STR
    float* wa2T = wp2T + NOSC * ENC_W2STR;
    float* xs   = wa2T + NOSC * ENC_W2STR;     // 2 x 128
    float* hs   = xs + 256;                    // 2 x 128  (h | ha per row)

    int tid = threadIdx.x;
    for (int idx = tid; idx < DIM * HID; idx += 256) {
        int k = idx >> 6, j = idx & 63;
        wp1T[j * ENC_W1STR + k] = Wp1[idx];
        wa1T[j * ENC_W1STR + k] = Wa1[idx];
    }
    for (int idx = tid; idx < HID * NOSC; idx += 256) {
        int k = idx / NOSC, j = idx % NOSC;
        wp2T[j * ENC_W2STR + k] = Wp2[idx];
        wa2T[j * ENC_W2STR + k] = Wa2[idx];
    }

    int hf = tid >> 7;          // which of the 2 rows this thread serves
    int t  = tid & 127;

    for (int it = 0; it < 16; ++it) {
        int row = blockIdx.x * 32 + it * 2 + hf;
        bool isT = row < N_DET;
        const float* X = isT ? (det_t + (size_t)row * DIM)
                             : (det_t1 + (size_t)(row - N_DET) * DIM);
        __syncthreads();                 // protect xs/hs from previous iter
        xs[hf * 128 + t] = X[t];
        __syncthreads();

        // layer 1: t<64 -> phase h, t>=64 -> amp ha (amp only for t rows)
        {
            bool doAmp = (t >= 64);
            if (!doAmp || isT) {
                int j = doAmp ? (t - 64) : t;
                const float4* w4 = (const float4*)(doAmp ? &wa1T[j * ENC_W1STR]
                                                         : &wp1T[j * ENC_W1STR]);
                const float4* x4 = (const float4*)(xs + hf * 128);
                float acc = doAmp ? ba1[j] : bp1[j];
                #pragma unroll
                for (int k4 = 0; k4 < 32; ++k4) {
                    float4 w = w4[k4], x = x4[k4];
                    acc += w.x * x.x + w.y * x.y + w.z * x.z + w.w * x.w;
                }
                hs[hf * 128 + t] = fmaxf(acc, 0.0f);
            }
        }
        __syncthreads();

        // layer 2
        int lane = t & 31, wgrp = t >> 5;
        if (wgrp == 0 && lane < NOSC) {               // phase head
            const float4* w4 = (const float4*)&wp2T[lane * ENC_W2STR];
            const float4* h4 = (const float4*)(hs + hf * 128);
            float acc = bp2[lane];
            #pragma unroll
            for (int k4 = 0; k4 < 16; ++k4) {
                float4 w = w4[k4], h = h4[k4];
                acc += w.x * h.x + w.y * h.y + w.z * h.z + w.w * h.w;
            }
            float ph = mod2pi(acc);
            if (isT) {
                g_phase[row * NOSC + lane] = ph;
            } else {
                int col = row - N_DET;
                g_B[lane * N_DET + col]          = cosf(ph);
                g_B[(lane + NOSC) * N_DET + col] = sinf(ph);
            }
        } else if (wgrp == 1 && lane < NOSC && isT) { // amp head (t rows only)
            const float4* w4 = (const float4*)&wa2T[lane * ENC_W2STR];
            const float4* h4 = (const float4*)(hs + hf * 128 + 64);
            float acc = ba2[lane];
            #pragma unroll
            for (int k4 = 0; k4 < 16; ++k4) {
                float4 w = w4[k4], h = h4[k4];
                acc += w.x * h.x + w.y * h.y + w.z * h.z + w.w * h.w;
            }
            g_amp[row * NOSC + lane] = softplusf(acc);
        }
    }
}

// ---------------------------------------------------------------------------
// Evolve: 5 Kuramoto steps, one warp per row (lanes 0..27 active).
// Writes duplicated-pair A rows for the f32x2 GEMM.
// ---------------------------------------------------------------------------
__global__ void evolve_kernel() {
    int gw   = (blockIdx.x * blockDim.x + threadIdx.x) >> 5;
    int lane = threadIdx.x & 31;
    if (gw >= N_DET) return;
    bool act = lane < NOSC;

    float ph = act ? g_phase[gw * NOSC + lane] : 0.0f;
    float am = act ? g_amp[gw * NOSC + lane] : 0.0f;
    float omega = TWO_PI_F * (lane < 4 ? 2.0f : (lane < 12 ? 6.0f : 40.0f));

    #pragma unroll
    for (int s = 0; s < 5; ++s) {
        float c  = act ? cosf(ph) : 0.0f;
        float sn = act ? sinf(ph) : 0.0f;
        float sc = c, ss = sn;
        #pragma unroll
        for (int off = 16; off; off >>= 1) {
            sc += __shfl_down_sync(0xFFFFFFFFu, sc, off);
            ss += __shfl_down_sync(0xFFFFFFFFu, ss, off);
        }
        sc = __shfl_sync(0xFFFFFFFFu, sc, 0);
        ss = __shfl_sync(0xFFFFFFFFu, ss, 0);
        float mc = sc / 28.0f, ms = ss / 28.0f;
        float coup = ms * c - mc * sn;
        ph = mod2pi(ph + 0.01f * (omega + am * coup));
    }
    if (act) {
        float c = cosf(ph), sn = sinf(ph);
        float* arow = g_A + (size_t)gw * 112;
        arow[2 * lane]     = c;  arow[2 * lane + 1]      = c;
        arow[56 + 2*lane]  = sn; arow[56 + 2*lane + 1]   = sn;
    }
}

// ---------------------------------------------------------------------------
// Similarity GEMM: 128x128 tile per block, 256 threads, 16x4 microtile as
// f32x2 pairs. Fused per-row max/argmax via packed-key atomicMax.
// ---------------------------------------------------------------------------
#define GEMM_SMEM_BYTES ((128*112 + 56*128) * 4)

__global__ __launch_bounds__(256, 2)
void gemm_kernel(float* __restrict__ sim) {
    extern __shared__ float smg[];
    float* As = smg;                 // 128 rows x 112 floats (dup pairs)
    float* Bs = smg + 128 * 112;     // 56 k-rows x 128 cols

    const int tid = threadIdx.x;
    const int tx = tid & 31;
    const int ty = tid >> 5;

    // load A tile (contiguous) and B tile (strided rows of 128)
    {
        const float4* gA = (const float4*)(g_A + (size_t)blockIdx.y * 128 * 112);
        float4* sA = (float4*)As;
        #pragma unroll
        for (int i = 0; i < 14; ++i) sA[tid + i * 256] = gA[tid + i * 256];

        float4* sB = (float4*)Bs;
        #pragma unroll
        for (int i = 0; i < 7; ++i) {
            int idx = tid + i * 256;           // 0..1791
            int k = idx >> 5, jq = idx & 31;
            sB[idx] = *(const float4*)(g_B + (size_t)k * N_DET + blockIdx.x * 128 + jq * 4);
        }
    }
    __syncthreads();

    unsigned long long acc[16][2];
    #pragma unroll
    for (int r = 0; r < 16; ++r) { acc[r][0] = 0ull; acc[r][1] = 0ull; }

    #pragma unroll 2
    for (int kp = 0; kp < 28; ++kp) {
        const float* b0 = Bs + (2 * kp) * 128;
        const float* b1 = b0 + 128;
        unsigned long long b00 = *(const unsigned long long*)(b0 + tx * 2);
        unsigned long long b01 = *(const unsigned long long*)(b0 + 64 + tx * 2);
        unsigned long long b10 = *(const unsigned long long*)(b1 + tx * 2);
        unsigned long long b11 = *(const unsigned long long*)(b1 + 64 + tx * 2);
        #pragma unroll
        for (int r = 0; r < 16; ++r) {
            ulonglong2 av = *(const ulonglong2*)(As + (ty * 16 + r) * 112 + 4 * kp);
            ffma2(acc[r][0], av.x, b00);
            ffma2(acc[r][1], av.x, b01);
            ffma2(acc[r][0], av.y, b10);
            ffma2(acc[r][1], av.y, b11);
        }
    }

    const float invden = 1.0f / DENOM_F;
    #pragma unroll
    for (int r = 0; r < 16; ++r) {
        int grow = blockIdx.y * 128 + ty * 16 + r;
        unsigned long long best = 0ull;
        #pragma unroll
        for (int c = 0; c < 2; ++c) {
            float2 v = *(float2*)&acc[r][c];
            v.x *= invden; v.y *= invden;
            int gcol = blockIdx.x * 128 + tx * 2 + 64 * c;
            *(float2*)(sim + (size_t)grow * N_DET + gcol) = v;
            unsigned long long k0 = ((unsigned long long)ordf(v.x) << 32) | (unsigned)(~(unsigned)gcol);
            unsigned long long k1 = ((unsigned long long)ordf(v.y) << 32) | (unsigned)(~(unsigned)(gcol + 1));
            unsigned long long kk = (k0 > k1) ? k0 : k1;
            if (kk > best) best = kk;
        }
        #pragma unroll
        for (int off = 16; off; off >>= 1) {
            unsigned long long o = __shfl_down_sync(0xFFFFFFFFu, best, off);
            if (o > best) best = o;
        }
        if (tx == 0) atomicMax(&g_rowbest[grow], best);
    }
}

// ---------------------------------------------------------------------------
// Parallel greedy match. Winner per column j = row with largest (sim, -i)
// among rows with argmax==j and sim > threshold. Exactly equals the scan.
// ---------------------------------------------------------------------------
__global__ void claim_kernel() {
    int i = blockIdx.x * blockDim.x + threadIdx.x;
    if (i >= N_DET) return;
    const unsigned ORD_THR = __float_as_uint(0.3f) | 0x80000000u;
    unsigned long long rb = g_rowbest[i];
    unsigned ordsim = (unsigned)(rb >> 32);
    if (ordsim > ORD_THR) {
        unsigned j = ~(unsigned)rb;
        unsigned long long claimkey = (rb & 0xFFFFFFFF00000000ull) | (unsigned)(~(unsigned)i);
        atomicMax(&g_colbest[j], claimkey);
    }
}

__global__ void resolve_kernel(float* __restrict__ matches) {
    int i = blockIdx.x * blockDim.x + threadIdx.x;
    if (i >= N_DET) return;
    const unsigned ORD_THR = __float_as_uint(0.3f) | 0x80000000u;
    unsigned long long rb = g_rowbest[i];
    unsigned ordsim = (unsigned)(rb >> 32);
    float m = -1.0f;
    if (ordsim > ORD_THR) {
        unsigned j = ~(unsigned)rb;
        unsigned long long claimkey = (rb & 0xFFFFFFFF00000000ull) | (unsigned)(~(unsigned)i);
        if (g_colbest[j] == claimkey) m = (float)j;
    }
    matches[i] = m;
}

// ---------------------------------------------------------------------------
extern "C" void kernel_launch(void* const* d_in, const int* in_sizes, int n_in,
                              void* d_out, int out_size) {
    const float* det_t  = (const float*)d_in[0];
    const float* det_t1 = (const float*)d_in[1];
    const float* Wp1 = (const float*)d_in[2];
    const float* bp1 = (const float*)d_in[3];
    const float* Wp2 = (const float*)d_in[4];
    const float* bp2 = (const float*)d_in[5];
    const float* Wa1 = (const float*)d_in[6];
    const float* ba1 = (const float*)d_in[7];
    const float* Wa2 = (const float*)d_in[8];
    const float* ba2 = (const float*)d_in[9];
    float* out = (float*)d_out;                 // [0,4096): matches, then sim

    static int attr_done = 0;
    // (idempotent, deterministic; not a stream op so safe under capture)
    cudaFuncSetAttribute(encode_kernel, cudaFuncAttributeMaxDynamicSharedMemorySize,
                         ENC_SMEM_FLOATS * 4);
    cudaFuncSetAttribute(gemm_kernel, cudaFuncAttributeMaxDynamicSharedMemorySize,
                         GEMM_SMEM_BYTES);
    (void)attr_done;

    init_kernel<<<16, 256>>>();
    encode_kernel<<<256, 256, ENC_SMEM_FLOATS * 4>>>(det_t, det_t1,
                                                     Wp1, bp1, Wp2, bp2,
                                                     Wa1, ba1, Wa2, ba2);
    evolve_kernel<<<512, 256>>>();
    gemm_kernel<<<dim3(32, 32), 256, GEMM_SMEM_BYTES>>>(out + N_DET);
    claim_kernel<<<16, 256>>>();
    resolve_kernel<<<16, 256>>>(out);
}